// round 15
// baseline (speedup 1.0000x reference)
#include <cuda_runtime.h>
#include <cuda_fp16.h>
#include <math.h>
#include <stdint.h>

#define SEQ    4096
#define DMODEL 768
#define NHEADS 12
#define HD     64
#define DFF    3072

// -------------------- scratch (no allocations allowed) ---------------------
__device__ __half g_xh[SEQ * DMODEL];
__device__ __half g_qkv[SEQ * 3 * DMODEL];
__device__ __half g_attn[SEQ * DMODEL];
__device__ __half g_ff1[SEQ * DFF];
__device__ __half g_wqkvT[3 * DMODEL * DMODEL];  // [2304][768]; q-rows pre-scaled by log2e/sqrt(d)
__device__ __half g_wff1T[DFF * DMODEL];         // [3072][768]
__device__ __half g_wff2T[DMODEL * DFF];         // [768][3072]

// -------------------------- helpers ----------------------------------------
__device__ __forceinline__ uint32_t smem_u32(const void* p) {
    uint32_t a;
    asm("{ .reg .u64 t; cvta.to.shared.u64 t, %1; cvt.u32.u64 %0, t; }" : "=r"(a) : "l"(p));
    return a;
}
__device__ __forceinline__ void cp_async16(uint32_t s, const void* g) {
    asm volatile("cp.async.cg.shared.global [%0], [%1], 16;" :: "r"(s), "l"(g));
}
#define CP_COMMIT() asm volatile("cp.async.commit_group;" ::: "memory")
#define CP_WAIT(n)  asm volatile("cp.async.wait_group %0;" :: "n"(n) : "memory")

__device__ __forceinline__ void mma_f16(float* d, const uint32_t* a, const uint32_t* b) {
    asm volatile(
        "mma.sync.aligned.m16n8k16.row.col.f32.f16.f16.f32 "
        "{%0,%1,%2,%3}, {%4,%5,%6,%7}, {%8,%9}, {%0,%1,%2,%3};"
        : "+f"(d[0]), "+f"(d[1]), "+f"(d[2]), "+f"(d[3])
        : "r"(a[0]), "r"(a[1]), "r"(a[2]), "r"(a[3]), "r"(b[0]), "r"(b[1]));
}
__device__ __forceinline__ void ldsm_x4(uint32_t* r, uint32_t a) {
    asm volatile("ldmatrix.sync.aligned.m8n8.x4.shared.b16 {%0,%1,%2,%3}, [%4];"
        : "=r"(r[0]), "=r"(r[1]), "=r"(r[2]), "=r"(r[3]) : "r"(a));
}
__device__ __forceinline__ void ldsm_x4_t(uint32_t* r, uint32_t a) {
    asm volatile("ldmatrix.sync.aligned.m8n8.x4.trans.shared.b16 {%0,%1,%2,%3}, [%4];"
        : "=r"(r[0]), "=r"(r[1]), "=r"(r[2]), "=r"(r[3]) : "r"(a));
}
__device__ __forceinline__ uint32_t h2_u32(__half2 h) { return *(uint32_t*)&h; }

// ---------------------------------------------------------------------------
// fp16 mma.sync GEMM, CTA tile (MT*32)x128x64, 8 warps (2Mx4N), ldmatrix,
// 3-stage cp.async pipeline, 2 CTAs/SM.
// MT = m-frags per warp: 4 -> 128x128 tile (smem 110592), 2 -> 64x128 (82944).
// ---------------------------------------------------------------------------
#define LR 72

template<int MT>
__global__ __launch_bounds__(256, 2) void mma_gemm(
    const __half* __restrict__ A, const __half* __restrict__ Bt,
    const float* __restrict__ bias, void* __restrict__ Cv,
    int M, int N, int K, int gelu, int half_out)
{
    const int BM = MT * 32;
    extern __shared__ __half hs[];
    __half* AsB = hs;                    // [3][BM][LR]
    __half* BsB = hs + 3 * BM * LR;      // [3][128][LR]

    const int tid  = threadIdx.x;
    const int wid  = tid >> 5;
    const int lane = tid & 31;
    const int g    = lane >> 2;
    const int t4   = lane & 3;

    const int m0 = blockIdx.y * BM;
    const int n0 = blockIdx.x * 128;
    const int wm = (wid >> 2) * (MT * 16);
    const int wn = (wid & 3) * 32;

    const int a_row = ((lane >> 3) & 1) * 8 + (lane & 7);
    const int a_col = (lane >> 4) * 8;
    const int b_row = ((lane >> 4) & 1) * 8 + (lane & 7);
    const int b_col = ((lane >> 3) & 1) * 8;

    float acc[MT][4][4];
#pragma unroll
    for (int i = 0; i < MT; i++)
#pragma unroll
        for (int j = 0; j < 4; j++)
#pragma unroll
            for (int r = 0; r < 4; r++) acc[i][j][r] = 0.f;

    const int NS = K >> 6;               // BK = 64

    auto load_stage = [&](int s) {
        const int buf = s % 3;
        const int k0 = s << 6;
        __half* as = AsB + buf * BM * LR;
        __half* bs = BsB + buf * 128 * LR;
#pragma unroll
        for (int it = 0; it < MT; it++) {           // A: BM rows x 8 chunks
            int idx = it * 256 + tid;
            int row = idx >> 3, cc = idx & 7;
            cp_async16(smem_u32(as) + (uint32_t)((row * LR + cc * 8) * 2),
                       A + (size_t)(m0 + row) * K + k0 + cc * 8);
        }
#pragma unroll
        for (int it = 0; it < 4; it++) {            // B: 128 rows x 8 chunks
            int idx = it * 256 + tid;
            int row = idx >> 3, cc = idx & 7;
            cp_async16(smem_u32(bs) + (uint32_t)((row * LR + cc * 8) * 2),
                       Bt + (size_t)(n0 + row) * K + k0 + cc * 8);
        }
        CP_COMMIT();
    };

    load_stage(0);
    if (NS > 1) load_stage(1);

    for (int s = 0; s < NS; s++) {
        if (s + 2 < NS)      { load_stage(s + 2); CP_WAIT(2); }
        else if (s + 1 < NS) { CP_WAIT(1); }
        else                 { CP_WAIT(0); }
        __syncthreads();

        const int buf = s % 3;
        const uint32_t abase = smem_u32(AsB + buf * BM * LR)
                             + (uint32_t)(((wm + a_row) * LR + a_col) * 2);
        const uint32_t bbase = smem_u32(BsB + buf * 128 * LR)
                             + (uint32_t)(((wn + b_row) * LR + b_col) * 2);

#pragma unroll
        for (int kk = 0; kk < 64; kk += 16) {
            uint32_t afr[MT][4];
#pragma unroll
            for (int mt = 0; mt < MT; mt++)
                ldsm_x4(afr[mt], abase + (uint32_t)((mt * 16 * LR + kk) * 2));
            uint32_t bfr[2][4];
#pragma unroll
            for (int ntp = 0; ntp < 2; ntp++)
                ldsm_x4(bfr[ntp], bbase + (uint32_t)((ntp * 16 * LR + kk) * 2));
#pragma unroll
            for (int mt = 0; mt < MT; mt++)
#pragma unroll
                for (int ntp = 0; ntp < 2; ntp++) {
                    mma_f16(acc[mt][2 * ntp    ], afr[mt], bfr[ntp]);
                    mma_f16(acc[mt][2 * ntp + 1], afr[mt], bfr[ntp] + 2);
                }
        }
        __syncthreads();
    }

#pragma unroll
    for (int mt = 0; mt < MT; mt++) {
#pragma unroll
        for (int nt = 0; nt < 4; nt++) {
            const int col = n0 + wn + nt * 8 + t4 * 2;
            const float b0 = bias[col], b1 = bias[col + 1];
#pragma unroll
            for (int h = 0; h < 2; h++) {
                const int row = m0 + wm + mt * 16 + g + h * 8;
                float v0 = acc[mt][nt][h * 2 + 0] + b0;
                float v1 = acc[mt][nt][h * 2 + 1] + b1;
                if (gelu) {
                    v0 = 0.5f * v0 * (1.f + erff(v0 * 0.70710678118654752f));
                    v1 = 0.5f * v1 * (1.f + erff(v1 * 0.70710678118654752f));
                }
                if (half_out) {
                    *(__half2*)((__half*)Cv + (size_t)row * N + col) = __floats2half2_rn(v0, v1);
                } else {
                    *(float2*)((float*)Cv + (size_t)row * N + col) = make_float2(v0, v1);
                }
            }
        }
    }
}

// ---------------------------------------------------------------------------
// Fused prep: one launch does x->half plus all three weight transposes.
// ---------------------------------------------------------------------------
#define PREP_BLOCKS (3072 + 1728 + 2304 + 2304)

__global__ __launch_bounds__(256) void prep_kernel(
    const float* __restrict__ x,     __half* __restrict__ xh,
    const float* __restrict__ wqkv,  __half* __restrict__ wqkvT,
    const float* __restrict__ wff1,  __half* __restrict__ wff1T,
    const float* __restrict__ wff2,  __half* __restrict__ wff2T,
    float qscale)
{
    int b = blockIdx.x;
    const int tid = threadIdx.x;

    if (b < 3072) {                       // x -> half
        int i = (b * 256 + tid) * 4;
        float4 v = *(const float4*)(x + i);
        __half2 a = __floats2half2_rn(v.x, v.y);
        __half2 c = __floats2half2_rn(v.z, v.w);
        *(uint2*)(xh + i) = make_uint2(*(uint32_t*)&a, *(uint32_t*)&c);
        return;
    }
    b -= 3072;

    const float* in; __half* out;
    int R, C, tilesX; float scale; int scale_rows;
    if (b < 1728)      { in = wqkv; out = wqkvT; R = DMODEL; C = 3 * DMODEL; tilesX = 72; scale = qscale; scale_rows = DMODEL; }
    else if (b < 4032) { b -= 1728; in = wff1; out = wff1T; R = DMODEL; C = DFF;    tilesX = 96; scale = 1.f; scale_rows = 0; }
    else               { b -= 4032; in = wff2; out = wff2T; R = DFF;    C = DMODEL; tilesX = 24; scale = 1.f; scale_rows = 0; }

    __shared__ float t[32][33];
    const int c0 = (b % tilesX) * 32, r0 = (b / tilesX) * 32;
    const int xl = tid & 31, yl = tid >> 5;
#pragma unroll
    for (int i = 0; i < 32; i += 8)
        t[yl + i][xl] = in[(size_t)(r0 + yl + i) * C + c0 + xl];
    __syncthreads();
#pragma unroll
    for (int i = 0; i < 32; i += 8) {
        const int orow = c0 + yl + i;
        float v = t[xl][yl + i];
        if (orow < scale_rows) v *= scale;
        out[(size_t)orow * R + r0 + xl] = __float2half_rn(v);
    }
}

// ---------------------------------------------------------------------------
// Flash attention (round-11 proven numerics): softmax in exp2 domain (fp32
// exp2f), P packed to half after. Block = 128 q x 1 head, 8 warps.
// KV 128-row tiles dbl-buffered. smem = 92160 B.
// ---------------------------------------------------------------------------
#define AR 72
#define ATT_SMEM ((128 * AR + 2 * 128 * AR + 2 * 128 * AR) * 2)
#define KVT 128

__global__ __launch_bounds__(256) void attn_mma(const __half* __restrict__ qkv,
                                                __half* __restrict__ out)
{
    extern __shared__ __half sh[];
    __half* Qs = sh;
    __half* Ks = sh + 128 * AR;
    __half* Vs = sh + 128 * AR + 2 * KVT * AR;

    const int h    = blockIdx.y;
    const int q0   = blockIdx.x * 128;
    const int tid  = threadIdx.x;
    const int wid  = tid >> 5;
    const int lane = tid & 31;
    const int g    = lane >> 2;
    const int t4   = lane & 3;
    const int r0   = wid * 16;

    const int a_row = ((lane >> 3) & 1) * 8 + (lane & 7);
    const int a_col = (lane >> 4) * 8;
    const int b_row = ((lane >> 4) & 1) * 8 + (lane & 7);
    const int b_col = ((lane >> 3) & 1) * 8;

#pragma unroll
    for (int it = 0; it < 4; it++) {
        int idx = it * 256 + tid;
        int row = idx >> 3, c = (idx & 7) * 8;
        cp_async16(smem_u32(Qs + row * AR + c),
                   qkv + (size_t)(q0 + row) * (3 * DMODEL) + h * HD + c);
    }

    auto load_KV = [&](int jt, int buf) {
        __half* ks = Ks + buf * KVT * AR;
        __half* vs = Vs + buf * KVT * AR;
#pragma unroll
        for (int it = 0; it < 4; it++) {
            int idx = it * 256 + tid;
            int row = idx >> 3, c = (idx & 7) * 8;
            const __half* base = qkv + (size_t)(jt * KVT + row) * (3 * DMODEL) + DMODEL + h * HD + c;
            cp_async16(smem_u32(ks + row * AR + c), base);
            cp_async16(smem_u32(vs + row * AR + c), base + DMODEL);
        }
        CP_COMMIT();
    };

    float oacc[8][4];
    float m0r = -INFINITY, m1r = -INFINITY, l0 = 0.f, l1 = 0.f;
#pragma unroll
    for (int nt = 0; nt < 8; nt++)
#pragma unroll
        for (int r = 0; r < 4; r++) oacc[nt][r] = 0.f;

    load_KV(0, 0);

    const uint32_t qbase = smem_u32(Qs) + (uint32_t)(((r0 + a_row) * AR + a_col) * 2);

    const int NT = SEQ / KVT;
    for (int jt = 0; jt < NT; jt++) {
        const int buf = jt & 1, nbuf = buf ^ 1;
        if (jt + 1 < NT) { load_KV(jt + 1, nbuf); CP_WAIT(1); }
        else             { CP_WAIT(0); }
        __syncthreads();

        const uint32_t kbase = smem_u32(Ks + buf * KVT * AR) + (uint32_t)((b_row * AR + b_col) * 2);
        const uint32_t vbase = smem_u32(Vs + buf * KVT * AR) + (uint32_t)((a_row * AR + a_col) * 2);

        float sacc[16][4];
#pragma unroll
        for (int nt = 0; nt < 16; nt++)
#pragma unroll
            for (int r = 0; r < 4; r++) sacc[nt][r] = 0.f;

#pragma unroll
        for (int kk = 0; kk < 64; kk += 16) {
            uint32_t afr[4];
            ldsm_x4(afr, qbase + (uint32_t)(kk * 2));
#pragma unroll
            for (int ntp = 0; ntp < 8; ntp++) {
                uint32_t bfr[4];
                ldsm_x4(bfr, kbase + (uint32_t)((ntp * 16 * AR + kk) * 2));
                mma_f16(sacc[2 * ntp    ], afr, bfr);
                mma_f16(sacc[2 * ntp + 1], afr, bfr + 2);
            }
        }

        // scores in log2 domain (log2e folded into Q weights)
        float mx0 = -INFINITY, mx1 = -INFINITY;
#pragma unroll
        for (int nt = 0; nt < 16; nt++) {
            mx0 = fmaxf(mx0, fmaxf(sacc[nt][0], sacc[nt][1]));
            mx1 = fmaxf(mx1, fmaxf(sacc[nt][2], sacc[nt][3]));
        }
#pragma unroll
        for (int o = 1; o <= 2; o <<= 1) {
            mx0 = fmaxf(mx0, __shfl_xor_sync(0xffffffffu, mx0, o));
            mx1 = fmaxf(mx1, __shfl_xor_sync(0xffffffffu, mx1, o));
        }
        const float mn0 = fmaxf(m0r, mx0), mn1 = fmaxf(m1r, mx1);
        const float c0 = exp2f(m0r - mn0), c1 = exp2f(m1r - mn1);
        m0r = mn0; m1r = mn1;
        float rs0 = 0.f, rs1 = 0.f;
#pragma unroll
        for (int nt = 0; nt < 16; nt++) {
            sacc[nt][0] = exp2f(sacc[nt][0] - mn0);
            sacc[nt][1] = exp2f(sacc[nt][1] - mn0);
            sacc[nt][2] = exp2f(sacc[nt][2] - mn1);
            sacc[nt][3] = exp2f(sacc[nt][3] - mn1);
            rs0 += sacc[nt][0] + sacc[nt][1];
            rs1 += sacc[nt][2] + sacc[nt][3];
        }
#pragma unroll
        for (int o = 1; o <= 2; o <<= 1) {
            rs0 += __shfl_xor_sync(0xffffffffu, rs0, o);
            rs1 += __shfl_xor_sync(0xffffffffu, rs1, o);
        }
        l0 = l0 * c0 + rs0;
        l1 = l1 * c1 + rs1;
#pragma unroll
        for (int nt = 0; nt < 8; nt++) {
            oacc[nt][0] *= c0; oacc[nt][1] *= c0;
            oacc[nt][2] *= c1; oacc[nt][3] *= c1;
        }

        uint32_t pa[8][4];
#pragma unroll
        for (int ntk = 0; ntk < 8; ntk++) {
            pa[ntk][0] = h2_u32(__floats2half2_rn(sacc[2 * ntk    ][0], sacc[2 * ntk    ][1]));
            pa[ntk][1] = h2_u32(__floats2half2_rn(sacc[2 * ntk    ][2], sacc[2 * ntk    ][3]));
            pa[ntk][2] = h2_u32(__floats2half2_rn(sacc[2 * ntk + 1][0], sacc[2 * ntk + 1][1]));
            pa[ntk][3] = h2_u32(__floats2half2_rn(sacc[2 * ntk + 1][2], sacc[2 * ntk + 1][3]));
        }

#pragma unroll
        for (int ntk = 0; ntk < 8; ntk++) {
#pragma unroll
            for (int ndp = 0; ndp < 4; ndp++) {
                uint32_t bfr[4];
                ldsm_x4_t(bfr, vbase + (uint32_t)((ntk * 16 * AR + ndp * 16) * 2));
                mma_f16(oacc[2 * ndp    ], pa[ntk], bfr);
                mma_f16(oacc[2 * ndp + 1], pa[ntk], bfr + 2);
            }
        }
        __syncthreads();
    }

    const float i0 = 1.f / l0, i1 = 1.f / l1;
#pragma unroll
    for (int nt = 0; nt < 8; nt++) {
        const int col = h * HD + nt * 8 + 2 * t4;
        *(__half2*)(out + (size_t)(q0 + r0 + g    ) * DMODEL + col) =
            __floats2half2_rn(oacc[nt][0] * i0, oacc[nt][1] * i0);
        *(__half2*)(out + (size_t)(q0 + r0 + g + 8) * DMODEL + col) =
            __floats2half2_rn(oacc[nt][2] * i1, oacc[nt][3] * i1);
    }
}

// ---------------------------------------------------------------------------
extern "C" void kernel_launch(void* const* d_in, const int* in_sizes, int n_in,
                              void* d_out, int out_size)
{
    const float* x     = (const float*)d_in[0];
    const float* w_qkv = (const float*)d_in[1];
    const float* b_qkv = (const float*)d_in[2];
    const float* w_ff1 = (const float*)d_in[3];
    const float* b_ff1 = (const float*)d_in[4];
    const float* w_ff2 = (const float*)d_in[5];
    const float* b_ff2 = (const float*)d_in[6];
    float* out = (float*)d_out;

    __half *xh, *qkv, *attn, *ff1, *wqkvT, *wff1T, *wff2T;
    cudaGetSymbolAddress((void**)&xh,    g_xh);
    cudaGetSymbolAddress((void**)&qkv,   g_qkv);
    cudaGetSymbolAddress((void**)&attn,  g_attn);
    cudaGetSymbolAddress((void**)&ff1,   g_ff1);
    cudaGetSymbolAddress((void**)&wqkvT, g_wqkvT);
    cudaGetSymbolAddress((void**)&wff1T, g_wff1T);
    cudaGetSymbolAddress((void**)&wff2T, g_wff2T);

    const int GEMM_SMEM4 = 3 * (128 + 128) * LR * 2;   // 110592
    const int GEMM_SMEM2 = 3 * (64 + 128) * LR * 2;    // 82944
    cudaFuncSetAttribute(mma_gemm<4>, cudaFuncAttributeMaxDynamicSharedMemorySize, GEMM_SMEM4);
    cudaFuncSetAttribute(mma_gemm<2>, cudaFuncAttributeMaxDynamicSharedMemorySize, GEMM_SMEM2);
    cudaFuncSetAttribute(attn_mma, cudaFuncAttributeMaxDynamicSharedMemorySize, ATT_SMEM);

    // 1/sqrt(768) * log2(e): softmax runs in exp2 domain
    const float qscale = 1.4426950408889634f / sqrtf(768.0f);

    prep_kernel<<<PREP_BLOCKS, 256>>>(x, xh, w_qkv, wqkvT, w_ff1, wff1T, w_ff2, wff2T, qscale);

    // 1) QKV -> half (128x128 tile)
    mma_gemm<4><<<dim3(3 * DMODEL / 128, SEQ / 128), 256, GEMM_SMEM4>>>(
        xh, wqkvT, b_qkv, qkv, SEQ, 3 * DMODEL, DMODEL, 0, 1);

    // 2) Attention -> half
    attn_mma<<<dim3(SEQ / 128, NHEADS), 256, ATT_SMEM>>>(qkv, attn);

    // 3) FF1 + exact GELU -> half (128x128 tile)
    mma_gemm<4><<<dim3(DFF / 128, SEQ / 128), 256, GEMM_SMEM4>>>(
        attn, wff1T, b_ff1, ff1, SEQ, DFF, DMODEL, 1, 1);

    // 4) FF2 -> fp32 out (64x128 tile: 384 CTAs, fills the chip)
    mma_gemm<2><<<dim3(DMODEL / 128, SEQ / 64), 256, GEMM_SMEM2>>>(
        ff1, wff2T, b_ff2, out, SEQ, DMODEL, DFF, 0, 0);
}

// round 16
// speedup vs baseline: 1.0419x; 1.0419x over previous
#include <cuda_runtime.h>
#include <cuda_fp16.h>
#include <math.h>
#include <stdint.h>

#define SEQ    4096
#define DMODEL 768
#define NHEADS 12
#define HD     64
#define DFF    3072

// -------------------- scratch (no allocations allowed) ---------------------
__device__ __half g_xh[SEQ * DMODEL];
__device__ __half g_qkv[SEQ * 3 * DMODEL];
__device__ __half g_attn[SEQ * DMODEL];
__device__ __half g_ff1[SEQ * DFF];
__device__ __half g_wqkvT[3 * DMODEL * DMODEL];  // [2304][768]; q-rows pre-scaled by log2e/sqrt(d)
__device__ __half g_wff1T[DFF * DMODEL];         // [3072][768]
__device__ __half g_wff2T[DMODEL * DFF];         // [768][3072]

// -------------------------- helpers ----------------------------------------
__device__ __forceinline__ uint32_t smem_u32(const void* p) {
    uint32_t a;
    asm("{ .reg .u64 t; cvta.to.shared.u64 t, %1; cvt.u32.u64 %0, t; }" : "=r"(a) : "l"(p));
    return a;
}
__device__ __forceinline__ void cp_async16(uint32_t s, const void* g) {
    asm volatile("cp.async.cg.shared.global [%0], [%1], 16;" :: "r"(s), "l"(g));
}
#define CP_COMMIT() asm volatile("cp.async.commit_group;" ::: "memory")
#define CP_WAIT(n)  asm volatile("cp.async.wait_group %0;" :: "n"(n) : "memory")

__device__ __forceinline__ void mma_f16(float* d, const uint32_t* a, const uint32_t* b) {
    asm volatile(
        "mma.sync.aligned.m16n8k16.row.col.f32.f16.f16.f32 "
        "{%0,%1,%2,%3}, {%4,%5,%6,%7}, {%8,%9}, {%0,%1,%2,%3};"
        : "+f"(d[0]), "+f"(d[1]), "+f"(d[2]), "+f"(d[3])
        : "r"(a[0]), "r"(a[1]), "r"(a[2]), "r"(a[3]), "r"(b[0]), "r"(b[1]));
}
__device__ __forceinline__ void ldsm_x4(uint32_t* r, uint32_t a) {
    asm volatile("ldmatrix.sync.aligned.m8n8.x4.shared.b16 {%0,%1,%2,%3}, [%4];"
        : "=r"(r[0]), "=r"(r[1]), "=r"(r[2]), "=r"(r[3]) : "r"(a));
}
__device__ __forceinline__ void ldsm_x4_t(uint32_t* r, uint32_t a) {
    asm volatile("ldmatrix.sync.aligned.m8n8.x4.trans.shared.b16 {%0,%1,%2,%3}, [%4];"
        : "=r"(r[0]), "=r"(r[1]), "=r"(r[2]), "=r"(r[3]) : "r"(a));
}
__device__ __forceinline__ uint32_t h2_u32(__half2 h) { return *(uint32_t*)&h; }

// ---------------------------------------------------------------------------
// fp16 mma.sync GEMM, CTA tile 128x128x64, 8 warps (2Mx4N), ldmatrix frags,
// 3-stage cp.async pipeline, 2 CTAs/SM. smem = 110592 B.  (round-14 proven)
// ---------------------------------------------------------------------------
#define LR 72

__global__ __launch_bounds__(256, 2) void mma_gemm(
    const __half* __restrict__ A, const __half* __restrict__ Bt,
    const float* __restrict__ bias, void* __restrict__ Cv,
    int M, int N, int K, int gelu, int half_out)
{
    extern __shared__ __half hs[];
    __half* AsB = hs;                    // [3][128][LR]
    __half* BsB = hs + 3 * 128 * LR;

    const int tid  = threadIdx.x;
    const int wid  = tid >> 5;
    const int lane = tid & 31;
    const int g    = lane >> 2;
    const int t4   = lane & 3;

    const int m0 = blockIdx.y * 128;
    const int n0 = blockIdx.x * 128;
    const int wm = (wid >> 2) * 64;
    const int wn = (wid & 3) * 32;

    const int a_row = ((lane >> 3) & 1) * 8 + (lane & 7);
    const int a_col = (lane >> 4) * 8;
    const int b_row = ((lane >> 4) & 1) * 8 + (lane & 7);
    const int b_col = ((lane >> 3) & 1) * 8;

    float acc[4][4][4];
#pragma unroll
    for (int i = 0; i < 4; i++)
#pragma unroll
        for (int j = 0; j < 4; j++)
#pragma unroll
            for (int r = 0; r < 4; r++) acc[i][j][r] = 0.f;

    const int NS = K >> 6;               // BK = 64

    auto load_stage = [&](int s) {
        const int buf = s % 3;
        const int k0 = s << 6;
        __half* as = AsB + buf * 128 * LR;
        __half* bs = BsB + buf * 128 * LR;
#pragma unroll
        for (int it = 0; it < 4; it++) {
            int idx = it * 256 + tid;        // 0..1023
            int row = idx >> 3, cc = idx & 7;
            uint32_t so = (uint32_t)((row * LR + cc * 8) * 2);
            cp_async16(smem_u32(as) + so, A  + (size_t)(m0 + row) * K + k0 + cc * 8);
            cp_async16(smem_u32(bs) + so, Bt + (size_t)(n0 + row) * K + k0 + cc * 8);
        }
        CP_COMMIT();
    };

    load_stage(0);
    if (NS > 1) load_stage(1);

    for (int s = 0; s < NS; s++) {
        if (s + 2 < NS)      { load_stage(s + 2); CP_WAIT(2); }
        else if (s + 1 < NS) { CP_WAIT(1); }
        else                 { CP_WAIT(0); }
        __syncthreads();

        const int buf = s % 3;
        const uint32_t abase = smem_u32(AsB + buf * 128 * LR)
                             + (uint32_t)(((wm + a_row) * LR + a_col) * 2);
        const uint32_t bbase = smem_u32(BsB + buf * 128 * LR)
                             + (uint32_t)(((wn + b_row) * LR + b_col) * 2);

#pragma unroll
        for (int kk = 0; kk < 64; kk += 16) {
            uint32_t afr[4][4];
#pragma unroll
            for (int mt = 0; mt < 4; mt++)
                ldsm_x4(afr[mt], abase + (uint32_t)((mt * 16 * LR + kk) * 2));
            uint32_t bfr[2][4];
#pragma unroll
            for (int ntp = 0; ntp < 2; ntp++)
                ldsm_x4(bfr[ntp], bbase + (uint32_t)((ntp * 16 * LR + kk) * 2));
#pragma unroll
            for (int mt = 0; mt < 4; mt++)
#pragma unroll
                for (int ntp = 0; ntp < 2; ntp++) {
                    mma_f16(acc[mt][2 * ntp    ], afr[mt], bfr[ntp]);
                    mma_f16(acc[mt][2 * ntp + 1], afr[mt], bfr[ntp] + 2);
                }
        }
        __syncthreads();
    }

#pragma unroll
    for (int mt = 0; mt < 4; mt++) {
#pragma unroll
        for (int nt = 0; nt < 4; nt++) {
            const int col = n0 + wn + nt * 8 + t4 * 2;
            const float b0 = bias[col], b1 = bias[col + 1];
#pragma unroll
            for (int h = 0; h < 2; h++) {
                const int row = m0 + wm + mt * 16 + g + h * 8;
                float v0 = acc[mt][nt][h * 2 + 0] + b0;
                float v1 = acc[mt][nt][h * 2 + 1] + b1;
                if (gelu) {
                    v0 = 0.5f * v0 * (1.f + erff(v0 * 0.70710678118654752f));
                    v1 = 0.5f * v1 * (1.f + erff(v1 * 0.70710678118654752f));
                }
                if (half_out) {
                    *(__half2*)((__half*)Cv + (size_t)row * N + col) = __floats2half2_rn(v0, v1);
                } else {
                    *(float2*)((float*)Cv + (size_t)row * N + col) = make_float2(v0, v1);
                }
            }
        }
    }
}

// ---------------------------------------------------------------------------
// Fused prep: one launch does x->half plus all three weight transposes.
// ---------------------------------------------------------------------------
#define PREP_BLOCKS (3072 + 1728 + 2304 + 2304)

__global__ __launch_bounds__(256) void prep_kernel(
    const float* __restrict__ x,     __half* __restrict__ xh,
    const float* __restrict__ wqkv,  __half* __restrict__ wqkvT,
    const float* __restrict__ wff1,  __half* __restrict__ wff1T,
    const float* __restrict__ wff2,  __half* __restrict__ wff2T,
    float qscale)
{
    int b = blockIdx.x;
    const int tid = threadIdx.x;

    if (b < 3072) {                       // x -> half
        int i = (b * 256 + tid) * 4;
        float4 v = *(const float4*)(x + i);
        __half2 a = __floats2half2_rn(v.x, v.y);
        __half2 c = __floats2half2_rn(v.z, v.w);
        *(uint2*)(xh + i) = make_uint2(*(uint32_t*)&a, *(uint32_t*)&c);
        return;
    }
    b -= 3072;

    const float* in; __half* out;
    int R, C, tilesX; float scale; int scale_rows;
    if (b < 1728)      { in = wqkv; out = wqkvT; R = DMODEL; C = 3 * DMODEL; tilesX = 72; scale = qscale; scale_rows = DMODEL; }
    else if (b < 4032) { b -= 1728; in = wff1; out = wff1T; R = DMODEL; C = DFF;    tilesX = 96; scale = 1.f; scale_rows = 0; }
    else               { b -= 4032; in = wff2; out = wff2T; R = DFF;    C = DMODEL; tilesX = 24; scale = 1.f; scale_rows = 0; }

    __shared__ float t[32][33];
    const int c0 = (b % tilesX) * 32, r0 = (b / tilesX) * 32;
    const int xl = tid & 31, yl = tid >> 5;
#pragma unroll
    for (int i = 0; i < 32; i += 8)
        t[yl + i][xl] = in[(size_t)(r0 + yl + i) * C + c0 + xl];
    __syncthreads();
#pragma unroll
    for (int i = 0; i < 32; i += 8) {
        const int orow = c0 + yl + i;
        float v = t[xl][yl + i];
        if (orow < scale_rows) v *= scale;
        out[(size_t)orow * R + r0 + xl] = __float2half_rn(v);
    }
}

// ---------------------------------------------------------------------------
// Flash attention: KV 64-row tiles double-buffered, 2 CTAs/SM via
// __launch_bounds__(256,2) (regs <= 128: sacc 32 + pa 16 + oacc 32).
// Softmax in exp2 domain (log2e folded into Q weights).
// smem: Qs 128x72 | Ks 2x64x72 | Vs 2x64x72 = 55296 B.
// ---------------------------------------------------------------------------
#define AR 72
#define KVT 64
#define ATT_SMEM ((128 * AR + 2 * KVT * AR + 2 * KVT * AR) * 2)

__global__ __launch_bounds__(256, 2) void attn_mma(const __half* __restrict__ qkv,
                                                   __half* __restrict__ out)
{
    extern __shared__ __half sh[];
    __half* Qs = sh;
    __half* Ks = sh + 128 * AR;
    __half* Vs = sh + 128 * AR + 2 * KVT * AR;

    const int h    = blockIdx.y;
    const int q0   = blockIdx.x * 128;
    const int tid  = threadIdx.x;
    const int wid  = tid >> 5;
    const int lane = tid & 31;
    const int g    = lane >> 2;
    const int t4   = lane & 3;
    const int r0   = wid * 16;

    const int a_row = ((lane >> 3) & 1) * 8 + (lane & 7);
    const int a_col = (lane >> 4) * 8;
    const int b_row = ((lane >> 4) & 1) * 8 + (lane & 7);
    const int b_col = ((lane >> 3) & 1) * 8;

#pragma unroll
    for (int it = 0; it < 4; it++) {
        int idx = it * 256 + tid;
        int row = idx >> 3, c = (idx & 7) * 8;
        cp_async16(smem_u32(Qs + row * AR + c),
                   qkv + (size_t)(q0 + row) * (3 * DMODEL) + h * HD + c);
    }

    auto load_KV = [&](int jt, int buf) {
        __half* ks = Ks + buf * KVT * AR;
        __half* vs = Vs + buf * KVT * AR;
#pragma unroll
        for (int it = 0; it < 2; it++) {
            int idx = it * 256 + tid;       // 0..511
            int row = idx >> 3, c = (idx & 7) * 8;
            const __half* base = qkv + (size_t)(jt * KVT + row) * (3 * DMODEL) + DMODEL + h * HD + c;
            cp_async16(smem_u32(ks + row * AR + c), base);
            cp_async16(smem_u32(vs + row * AR + c), base + DMODEL);
        }
        CP_COMMIT();
    };

    float oacc[8][4];
    float m0r = -INFINITY, m1r = -INFINITY, l0 = 0.f, l1 = 0.f;
#pragma unroll
    for (int nt = 0; nt < 8; nt++)
#pragma unroll
        for (int r = 0; r < 4; r++) oacc[nt][r] = 0.f;

    load_KV(0, 0);

    const uint32_t qbase = smem_u32(Qs) + (uint32_t)(((r0 + a_row) * AR + a_col) * 2);

    const int NT = SEQ / KVT;
    for (int jt = 0; jt < NT; jt++) {
        const int buf = jt & 1, nbuf = buf ^ 1;
        if (jt + 1 < NT) { load_KV(jt + 1, nbuf); CP_WAIT(1); }
        else             { CP_WAIT(0); }
        __syncthreads();

        const uint32_t kbase = smem_u32(Ks + buf * KVT * AR) + (uint32_t)((b_row * AR + b_col) * 2);
        const uint32_t vbase = smem_u32(Vs + buf * KVT * AR) + (uint32_t)((a_row * AR + a_col) * 2);

        // ---- S = Q K^T : 16 q rows x 64 kv per warp
        float sacc[8][4];
#pragma unroll
        for (int nt = 0; nt < 8; nt++)
#pragma unroll
            for (int r = 0; r < 4; r++) sacc[nt][r] = 0.f;

#pragma unroll
        for (int kk = 0; kk < 64; kk += 16) {
            uint32_t afr[4];
            ldsm_x4(afr, qbase + (uint32_t)(kk * 2));
#pragma unroll
            for (int ntp = 0; ntp < 4; ntp++) {
                uint32_t bfr[4];
                ldsm_x4(bfr, kbase + (uint32_t)((ntp * 16 * AR + kk) * 2));
                mma_f16(sacc[2 * ntp    ], afr, bfr);
                mma_f16(sacc[2 * ntp + 1], afr, bfr + 2);
            }
        }

        // ---- online softmax (rows g, g+8), log2 domain
        float mx0 = -INFINITY, mx1 = -INFINITY;
#pragma unroll
        for (int nt = 0; nt < 8; nt++) {
            mx0 = fmaxf(mx0, fmaxf(sacc[nt][0], sacc[nt][1]));
            mx1 = fmaxf(mx1, fmaxf(sacc[nt][2], sacc[nt][3]));
        }
#pragma unroll
        for (int o = 1; o <= 2; o <<= 1) {
            mx0 = fmaxf(mx0, __shfl_xor_sync(0xffffffffu, mx0, o));
            mx1 = fmaxf(mx1, __shfl_xor_sync(0xffffffffu, mx1, o));
        }
        const float mn0 = fmaxf(m0r, mx0), mn1 = fmaxf(m1r, mx1);
        const float c0 = exp2f(m0r - mn0), c1 = exp2f(m1r - mn1);
        m0r = mn0; m1r = mn1;
        float rs0 = 0.f, rs1 = 0.f;
#pragma unroll
        for (int nt = 0; nt < 8; nt++) {
            sacc[nt][0] = exp2f(sacc[nt][0] - mn0);
            sacc[nt][1] = exp2f(sacc[nt][1] - mn0);
            sacc[nt][2] = exp2f(sacc[nt][2] - mn1);
            sacc[nt][3] = exp2f(sacc[nt][3] - mn1);
            rs0 += sacc[nt][0] + sacc[nt][1];
            rs1 += sacc[nt][2] + sacc[nt][3];
        }
#pragma unroll
        for (int o = 1; o <= 2; o <<= 1) {
            rs0 += __shfl_xor_sync(0xffffffffu, rs0, o);
            rs1 += __shfl_xor_sync(0xffffffffu, rs1, o);
        }
        l0 = l0 * c0 + rs0;
        l1 = l1 * c1 + rs1;
#pragma unroll
        for (int nt = 0; nt < 8; nt++) {
            oacc[nt][0] *= c0; oacc[nt][1] *= c0;
            oacc[nt][2] *= c1; oacc[nt][3] *= c1;
        }

        // ---- P -> fp16 A-fragments (register-only)
        uint32_t pa[4][4];
#pragma unroll
        for (int ntk = 0; ntk < 4; ntk++) {
            pa[ntk][0] = h2_u32(__floats2half2_rn(sacc[2 * ntk    ][0], sacc[2 * ntk    ][1]));
            pa[ntk][1] = h2_u32(__floats2half2_rn(sacc[2 * ntk    ][2], sacc[2 * ntk    ][3]));
            pa[ntk][2] = h2_u32(__floats2half2_rn(sacc[2 * ntk + 1][0], sacc[2 * ntk + 1][1]));
            pa[ntk][3] = h2_u32(__floats2half2_rn(sacc[2 * ntk + 1][2], sacc[2 * ntk + 1][3]));
        }

        // ---- O += P V
#pragma unroll
        for (int ntk = 0; ntk < 4; ntk++) {
#pragma unroll
            for (int ndp = 0; ndp < 4; ndp++) {
                uint32_t bfr[4];
                ldsm_x4_t(bfr, vbase + (uint32_t)((ntk * 16 * AR + ndp * 16) * 2));
                mma_f16(oacc[2 * ndp    ], pa[ntk], bfr);
                mma_f16(oacc[2 * ndp + 1], pa[ntk], bfr + 2);
            }
        }
        __syncthreads();
    }

    const float i0 = 1.f / l0, i1 = 1.f / l1;
#pragma unroll
    for (int nt = 0; nt < 8; nt++) {
        const int col = h * HD + nt * 8 + 2 * t4;
        *(__half2*)(out + (size_t)(q0 + r0 + g    ) * DMODEL + col) =
            __floats2half2_rn(oacc[nt][0] * i0, oacc[nt][1] * i0);
        *(__half2*)(out + (size_t)(q0 + r0 + g + 8) * DMODEL + col) =
            __floats2half2_rn(oacc[nt][2] * i1, oacc[nt][3] * i1);
    }
}

// ---------------------------------------------------------------------------
extern "C" void kernel_launch(void* const* d_in, const int* in_sizes, int n_in,
                              void* d_out, int out_size)
{
    const float* x     = (const float*)d_in[0];
    const float* w_qkv = (const float*)d_in[1];
    const float* b_qkv = (const float*)d_in[2];
    const float* w_ff1 = (const float*)d_in[3];
    const float* b_ff1 = (const float*)d_in[4];
    const float* w_ff2 = (const float*)d_in[5];
    const float* b_ff2 = (const float*)d_in[6];
    float* out = (float*)d_out;

    __half *xh, *qkv, *attn, *ff1, *wqkvT, *wff1T, *wff2T;
    cudaGetSymbolAddress((void**)&xh,    g_xh);
    cudaGetSymbolAddress((void**)&qkv,   g_qkv);
    cudaGetSymbolAddress((void**)&attn,  g_attn);
    cudaGetSymbolAddress((void**)&ff1,   g_ff1);
    cudaGetSymbolAddress((void**)&wqkvT, g_wqkvT);
    cudaGetSymbolAddress((void**)&wff1T, g_wff1T);
    cudaGetSymbolAddress((void**)&wff2T, g_wff2T);

    const int GEMM_SMEM = 3 * 2 * 128 * LR * 2;   // 110592
    cudaFuncSetAttribute(mma_gemm, cudaFuncAttributeMaxDynamicSharedMemorySize, GEMM_SMEM);
    cudaFuncSetAttribute(attn_mma, cudaFuncAttributeMaxDynamicSharedMemorySize, ATT_SMEM);

    // 1/sqrt(768) * log2(e): softmax runs in exp2 domain
    const float qscale = 1.4426950408889634f / sqrtf(768.0f);

    prep_kernel<<<PREP_BLOCKS, 256>>>(x, xh, w_qkv, wqkvT, w_ff1, wff1T, w_ff2, wff2T, qscale);

    // 1) QKV -> half
    mma_gemm<<<dim3(3 * DMODEL / 128, SEQ / 128), 256, GEMM_SMEM>>>(
        xh, wqkvT, b_qkv, qkv, SEQ, 3 * DMODEL, DMODEL, 0, 1);

    // 2) Attention -> half (2 CTAs/SM)
    attn_mma<<<dim3(SEQ / 128, NHEADS), 256, ATT_SMEM>>>(qkv, attn);

    // 3) FF1 + exact GELU -> half
    mma_gemm<<<dim3(DFF / 128, SEQ / 128), 256, GEMM_SMEM>>>(
        attn, wff1T, b_ff1, ff1, SEQ, DFF, DMODEL, 1, 1);

    // 4) FF2 -> fp32 out
    mma_gemm<<<dim3(DMODEL / 128, SEQ / 128), 256, GEMM_SMEM>>>(
        ff1, wff2T, b_ff2, out, SEQ, DMODEL, DFF, 0, 0);
}